// round 16
// baseline (speedup 1.0000x reference)
#include <cuda_runtime.h>
#include <cuda_bf16.h>
#include <math.h>
#include <stdint.h>

// ---------------------------------------------------------------------------
// Single-head self-attention, B=4, N=2048, E=1024, fp32.
// ALL GEMMs: int8 IMMA, two-digit fixed point (3 mmas / k32, 2 accumulators).
// R16: operands packed as 128x64B tiles (8KB, XOR swizzle); GEMM runs BK=64
// with a 4-stage cp.async.bulk pipeline (3-chunk prefetch), 2 CTAs/SM.
// ---------------------------------------------------------------------------

#define BATCH 4
#define SEQ   2048
#define EDIM  1024
#define MROWS (BATCH * SEQ)      // 8192
#define F3E   (3 * EDIM)         // 3072

// ---- device scratch (alloc-free rule) ----
// packed int8 digit arrays: [row>>7][k>>6] 8KB tiles (128 rows x 64B, XOR swz)
__device__ signed char  g_x1[MROWS * EDIM];
__device__ signed char  g_x2[MROWS * EDIM];
__device__ signed char  g_w1[F3E * EDIM];
__device__ signed char  g_w2[F3E * EDIM];
__device__ float        g_qkvf[(long long)MROWS * F3E];       // fp32 qkv
__device__ signed char  g_q1[MROWS * EDIM];
__device__ signed char  g_q2[MROWS * EDIM];
__device__ signed char  g_k1[MROWS * EDIM];
__device__ signed char  g_k2[MROWS * EDIM];
__device__ float        g_s[(long long)BATCH * SEQ * SEQ];    // scores fp32
__device__ signed char  g_p1[(long long)BATCH * SEQ * SEQ];   // P digit 1
__device__ signed char  g_p2[(long long)BATCH * SEQ * SEQ];   // P digit 2
__device__ float        g_pscale[MROWS];                      // per-row P scale
__device__ signed char  g_vt1[BATCH * EDIM * SEQ];            // V^T digit 1
__device__ signed char  g_vt2[BATCH * EDIM * SEQ];            // V^T digit 2
__device__ float        g_sx[MROWS];    // per-row x scale   (amax/127)
__device__ float        g_sw[F3E];      // per-row W scale
__device__ float        g_sq[MROWS];    // per-row q scale (x 1/32 folded)
__device__ float        g_sk[MROWS];    // per-row k scale
__device__ unsigned int g_amax[1];      // v global amax (fp32 bits)

// ---------------------------------------------------------------------------
// PTX helpers
// ---------------------------------------------------------------------------
__device__ __forceinline__ uint32_t s2u(const void* p) {
    uint32_t a;
    asm("{ .reg .u64 t; cvta.to.shared.u64 t, %1; cvt.u32.u64 %0, t; }"
        : "=r"(a) : "l"(p));
    return a;
}
__device__ __forceinline__ void ldsm4(uint32_t* r, uint32_t addr) {
    asm volatile("ldmatrix.sync.aligned.m8n8.x4.shared.b16 {%0,%1,%2,%3}, [%4];"
                 : "=r"(r[0]), "=r"(r[1]), "=r"(r[2]), "=r"(r[3]) : "r"(addr));
}
__device__ __forceinline__ void mma_s8(int* c, const uint32_t* a,
                                       uint32_t b0, uint32_t b1) {
    asm volatile("mma.sync.aligned.m16n8k32.row.col.s32.s8.s8.s32 "
                 "{%0,%1,%2,%3}, {%4,%5,%6,%7}, {%8,%9}, {%0,%1,%2,%3};"
                 : "+r"(c[0]), "+r"(c[1]), "+r"(c[2]), "+r"(c[3])
                 : "r"(a[0]), "r"(a[1]), "r"(a[2]), "r"(a[3]),
                   "r"(b0), "r"(b1));
}
// XOR swizzle within a 128x64B tile: row r, 16B slot s (0..3)
__device__ __forceinline__ uint32_t swz64(uint32_t r, uint32_t s) {
    return r * 64u + ((s ^ ((r >> 1) & 3u)) << 4);
}
// packed tile index: byte offset of (row, k) in an int8 array stored as
// row-tile-major 8KB tiles (128 rows x 64 k-bytes). kt = K/64.
__device__ __forceinline__ long long pkidx(int row, int k, int kt) {
    long long tile = (long long)(row >> 7) * kt + (k >> 6);
    uint32_t within = swz64((uint32_t)(row & 127), (uint32_t)((k >> 4) & 3))
                    + (uint32_t)(k & 15);
    return tile * 8192 + (long long)within;
}
// two-digit int8 quantization:  a ~= scale*(d1 + d2/254),  scale = amax/127
__device__ __forceinline__ void quant2(float a, float inv,
                                       signed char& d1, signed char& d2) {
    float t  = a * inv;
    float r1 = rintf(t);
    r1 = fminf(fmaxf(r1, -127.0f), 127.0f);
    float r2 = rintf((t - r1) * 254.0f);
    r2 = fminf(fmaxf(r2, -127.0f), 127.0f);
    d1 = (signed char)(int)r1;
    d2 = (signed char)(int)r2;
}

#define MBAR_INIT(mb, c) asm volatile("mbarrier.init.shared.b64 [%0], %1;" :: "r"(mb), "r"(c) : "memory")
#define MBAR_EXPECT(mb, bytes) asm volatile("mbarrier.arrive.expect_tx.shared.b64 _, [%0], %1;" :: "r"(mb), "r"(bytes) : "memory")
#define MBAR_WAIT(mb, ph) do {                                                   \
    asm volatile("{\n\t.reg .pred P;\n\t"                                        \
        "WL_%=:\n\t"                                                             \
        "mbarrier.try_wait.parity.shared.b64 P, [%0], %1;\n\t"                   \
        "@P bra.uni WD_%=;\n\t"                                                  \
        "bra.uni WL_%=;\n\t"                                                     \
        "WD_%=:\n\t}" :: "r"((uint32_t)(mb)), "r"((uint32_t)(ph)) : "memory");   \
} while (0)

__device__ __forceinline__ void bulk_ld(uint32_t dst, const void* src,
                                        uint32_t bytes, uint32_t mbar) {
    asm volatile("cp.async.bulk.shared::cluster.global.mbarrier::complete_tx::bytes "
                 "[%0], [%1], %2, [%3];"
                 :: "r"(dst), "l"(src), "r"(bytes), "r"(mbar) : "memory");
}

// ---------------------------------------------------------------------------
// init (v amax only)
// ---------------------------------------------------------------------------
__global__ void amax_init() {
    if (threadIdx.x == 0) g_amax[0] = 0u;
}

// ---------------------------------------------------------------------------
// Per-row quantize into PACKED tile layout. One block per 1024-elem row.
// ---------------------------------------------------------------------------
__global__ void __launch_bounds__(256)
quant_row(const float* __restrict__ in, long long inStride,
          signed char* __restrict__ d1, signed char* __restrict__ d2,
          float* __restrict__ scale, float preScale, int kt)
{
    const int row = blockIdx.x;
    const int t   = threadIdx.x;
    __shared__ float red[8];

    const float4 v = *(const float4*)(in + (long long)row * inStride + t * 4);
    float m = fmaxf(fmaxf(fabsf(v.x), fabsf(v.y)),
                    fmaxf(fabsf(v.z), fabsf(v.w)));
#pragma unroll
    for (int o = 16; o > 0; o >>= 1)
        m = fmaxf(m, __shfl_xor_sync(0xffffffffu, m, o));
    if ((t & 31) == 0) red[t >> 5] = m;
    __syncthreads();
    float amax = red[0];
#pragma unroll
    for (int i = 1; i < 8; i++) amax = fmaxf(amax, red[i]);
    amax = fmaxf(amax, 1e-20f);

    if (t == 0) scale[row] = (amax / 127.0f) * preScale;

    const float inv = 127.0f / amax;
    signed char a1, a2, b1, b2, c1, c2, e1, e2;
    quant2(v.x, inv, a1, a2);
    quant2(v.y, inv, b1, b2);
    quant2(v.z, inv, c1, c2);
    quant2(v.w, inv, e1, e2);
    const long long off = pkidx(row, t * 4, kt);
    *(char4*)(d1 + off) = make_char4(a1, b1, c1, e1);
    *(char4*)(d2 + off) = make_char4(a2, b2, c2, e2);
}

// ---------------------------------------------------------------------------
// int8 two-digit NT GEMM, bulk-copy 4-stage pipeline, BK=64.
//   C[m,n] = rowScaleA[m] * colScale(n) * alpha * (acc1 + acc2/254)
// A, B: packed 8KB tile arrays. aRows/bRows: rows per batch.
// Block 128(M)x64(N), 256 threads, 8 warps 4(M)x2(N), warp 32x32, 2 CTAs/SM.
// AMAXV=1: atomicMax |C| into g_amax[0] for cols >= 2048 (v region of qkv).
// ---------------------------------------------------------------------------
#define BMI 128
#define BNI 64
#define TILE_A 8192
#define TILE_B 4096
#define STAGE (2 * TILE_A + 2 * TILE_B)    // 24576
#define OFF_A1 0
#define OFF_A2 TILE_A
#define OFF_B1 (2 * TILE_A)
#define OFF_B2 (2 * TILE_A + TILE_B)
#define NSTG 4
#define SMEM_I8 (2048 + NSTG * STAGE)      // 100352

template <int AMAXV, int COLB>
__global__ void __launch_bounds__(256, 2)
gemm_i8(const signed char* __restrict__ A1, const signed char* __restrict__ A2,
        const signed char* __restrict__ B1, const signed char* __restrict__ B2,
        float* __restrict__ C,
        int aRows, int bRows, int ldc, int K,
        long long sC,
        const float* __restrict__ rowScaleA, int rsStride,
        const float* __restrict__ colScaleB, int csStride,
        float alpha)
{
    extern __shared__ char dsm[];
    const uint32_t raw   = s2u(dsm);
    const uint32_t base  = (raw + 1023u) & ~1023u;
    const uint32_t mbar0 = base;                 // 4 mbars at +0,8,16,24
    const uint32_t tile0 = base + 1024;

    const int tid  = threadIdx.x;
    const int wid  = tid >> 5;
    const int lane = tid & 31;
    const int wm   = wid & 3;       // 0..3 -> M (32 rows each)
    const int wn   = wid >> 2;      // 0..1 -> N (32 cols each)
    const int bz   = blockIdx.z;
    const int row0 = blockIdx.y * BMI;
    const int col0 = blockIdx.x * BNI;
    const int ktN  = K >> 6;
    const int aRow0 = bz * aRows + row0;          // multiple of 128
    const int bRow0 = bz * bRows + col0;          // multiple of 64
    const long long aTileRow = (long long)(aRow0 >> 7) * ktN;
    const long long bTileRow = (long long)(bRow0 >> 7) * ktN;
    const long long bSub = (bRow0 & 64) ? TILE_B : 0;

    if (tid == 0) {
#pragma unroll
        for (int s = 0; s < NSTG; s++) MBAR_INIT(mbar0 + s * 8, 1);
    }
    __syncthreads();

    auto issue = [&](int i) {
        const int st = i & (NSTG - 1);
        const uint32_t sb = tile0 + (uint32_t)st * STAGE;
        const uint32_t mb = mbar0 + (uint32_t)st * 8;
        MBAR_EXPECT(mb, (uint32_t)STAGE);
        const long long tA = (aTileRow + i) * 8192;
        const long long tB = (bTileRow + i) * 8192 + bSub;
        bulk_ld(sb + OFF_A1, A1 + tA, TILE_A, mb);
        bulk_ld(sb + OFF_A2, A2 + tA, TILE_A, mb);
        bulk_ld(sb + OFF_B1, B1 + tB, TILE_B, mb);
        bulk_ld(sb + OFF_B2, B2 + tB, TILE_B, mb);
    };

    const int nch = K >> 6;   // BK=64
    if (tid == 0) {
        issue(0);
        issue(1);
        issue(2);
    }

    int acc1[2][4][4], acc2[2][4][4];
#pragma unroll
    for (int t = 0; t < 2; t++)
#pragma unroll
        for (int u = 0; u < 4; u++)
#pragma unroll
            for (int j = 0; j < 4; j++) { acc1[t][u][j] = 0; acc2[t][u][j] = 0; }

    const uint32_t lrow  = (uint32_t)(lane & 15);
    const uint32_t lhalf = (uint32_t)(lane >> 4);

    for (int i = 0; i < nch; i++) {
        const int st = i & (NSTG - 1);
        MBAR_WAIT(mbar0 + (uint32_t)st * 8, (i >> 2) & 1);

        const uint32_t sb = tile0 + (uint32_t)st * STAGE;
        const uint32_t a1s = sb + OFF_A1;
        const uint32_t a2s = sb + OFF_A2;
        const uint32_t b1s = sb + OFF_B1;
        const uint32_t b2s = sb + OFF_B2;

#pragma unroll
        for (int ks = 0; ks < 2; ks++) {              // two k32 steps / chunk
            const uint32_t slot = (uint32_t)(ks * 2) + lhalf;
            uint32_t b1f[2][4], b2f[2][4];
#pragma unroll
            for (int g = 0; g < 2; g++) {
                const uint32_t r = (uint32_t)(wn * 32 + g * 16) + lrow;
                const uint32_t ro = swz64(r, slot);
                ldsm4(b1f[g], b1s + ro);
                ldsm4(b2f[g], b2s + ro);
            }
            uint32_t a1f[2][4], a2f[2][4];
#pragma unroll
            for (int t = 0; t < 2; t++) {
                const uint32_t r = (uint32_t)(wm * 32 + t * 16) + lrow;
                const uint32_t ro = swz64(r, slot);
                ldsm4(a1f[t], a1s + ro);
                ldsm4(a2f[t], a2s + ro);
            }
#pragma unroll
            for (int t = 0; t < 2; t++)
#pragma unroll
                for (int u = 0; u < 4; u++)
                    mma_s8(acc1[t][u], a1f[t], b1f[u >> 1][u & 1], b1f[u >> 1][(u & 1) + 2]);
#pragma unroll
            for (int t = 0; t < 2; t++)
#pragma unroll
                for (int u = 0; u < 4; u++)
                    mma_s8(acc2[t][u], a1f[t], b2f[u >> 1][u & 1], b2f[u >> 1][(u & 1) + 2]);
#pragma unroll
            for (int t = 0; t < 2; t++)
#pragma unroll
                for (int u = 0; u < 4; u++)
                    mma_s8(acc2[t][u], a2f[t], b1f[u >> 1][u & 1], b1f[u >> 1][(u & 1) + 2]);
        }

        __syncthreads();   // all warps done reading stage st
        if (tid == 0 && i + 3 < nch) issue(i + 3);
    }

    // ---- epilogue
    float sBglob = alpha;
    if (!COLB)
        sBglob *= fmaxf(__uint_as_float(g_amax[0]), 1e-20f) / 127.0f;
    const int er = lane >> 2;
    const int ec = 2 * (lane & 3);
    float lmax = 0.0f;
#pragma unroll
    for (int t = 0; t < 2; t++) {
        const int rloc = wm * 32 + t * 16 + er;
        const float s0 = rowScaleA[bz * rsStride + row0 + rloc] * sBglob;
        const float s1 = rowScaleA[bz * rsStride + row0 + rloc + 8] * sBglob;
        const long long r0r = row0 + rloc;
#pragma unroll
        for (int u = 0; u < 4; u++) {
            const int cc = col0 + wn * 32 + u * 8 + ec;
            float cs0 = 1.0f, cs1 = 1.0f;
            if (COLB) {
                cs0 = colScaleB[bz * csStride + cc];
                cs1 = colScaleB[bz * csStride + cc + 1];
            }
            float v[4];
            v[0] = s0 * cs0 * ((float)acc1[t][u][0] + (float)acc2[t][u][0] * (1.0f / 254.0f));
            v[1] = s0 * cs1 * ((float)acc1[t][u][1] + (float)acc2[t][u][1] * (1.0f / 254.0f));
            v[2] = s1 * cs0 * ((float)acc1[t][u][2] + (float)acc2[t][u][2] * (1.0f / 254.0f));
            v[3] = s1 * cs1 * ((float)acc1[t][u][3] + (float)acc2[t][u][3] * (1.0f / 254.0f));
            if (AMAXV && col0 >= 2048)
                lmax = fmaxf(fmaxf(fmaxf(fabsf(v[0]), fabsf(v[1])),
                                   fmaxf(fabsf(v[2]), fabsf(v[3]))), lmax);
            *(float2*)(C + (long long)bz * sC + r0r * ldc + cc)       = make_float2(v[0], v[1]);
            *(float2*)(C + (long long)bz * sC + (r0r + 8) * ldc + cc) = make_float2(v[2], v[3]);
        }
    }
    if (AMAXV && col0 >= 2048) {
#pragma unroll
        for (int o = 16; o > 0; o >>= 1)
            lmax = fmaxf(lmax, __shfl_xor_sync(0xffffffffu, lmax, o));
        if (lane == 0)
            atomicMax(&g_amax[0], __float_as_uint(lmax));
    }
}

// ---------------------------------------------------------------------------
// Row softmax (2048 cols) fp32 -> two-digit int8 P (packed, kt=32) + scale.
// ---------------------------------------------------------------------------
__global__ void __launch_bounds__(256)
softmax_q(const float* __restrict__ S, signed char* __restrict__ P1,
          signed char* __restrict__ P2, float* __restrict__ pscale)
{
    const int rowg = blockIdx.x;                    // global row 0..8191
    const long long roff = (long long)rowg * SEQ;
    const float* row = S + roff;
    const int t = threadIdx.x;
    __shared__ float red[8];

    float v[8];
    float4 a = *(const float4*)(row + t * 8);
    float4 b = *(const float4*)(row + t * 8 + 4);
    v[0] = a.x; v[1] = a.y; v[2] = a.z; v[3] = a.w;
    v[4] = b.x; v[5] = b.y; v[6] = b.z; v[7] = b.w;

    float m = -INFINITY;
#pragma unroll
    for (int i = 0; i < 8; i++) m = fmaxf(m, v[i]);
#pragma unroll
    for (int o = 16; o > 0; o >>= 1)
        m = fmaxf(m, __shfl_xor_sync(0xffffffffu, m, o));
    if ((t & 31) == 0) red[t >> 5] = m;
    __syncthreads();
    float rmax = red[0];
#pragma unroll
    for (int i = 1; i < 8; i++) rmax = fmaxf(rmax, red[i]);
    __syncthreads();

    float s = 0.0f;
#pragma unroll
    for (int i = 0; i < 8; i++) {
        v[i] = expf(v[i] - rmax);
        s += v[i];
    }
#pragma unroll
    for (int o = 16; o > 0; o >>= 1)
        s += __shfl_xor_sync(0xffffffffu, s, o);
    if ((t & 31) == 0) red[t >> 5] = s;
    __syncthreads();
    float rsum = 0.0f;
#pragma unroll
    for (int i = 0; i < 8; i++) rsum += red[i];

    if (t == 0) pscale[rowg] = (1.0f / rsum) / 127.0f;

    signed char d1[8], d2[8];
#pragma unroll
    for (int i = 0; i < 8; i++)
        quant2(v[i], 127.0f, d1[i], d2[i]);
    const long long off = pkidx(rowg, t * 8, SEQ / 64);
    *(uint2*)(P1 + off) = *(uint2*)d1;
    *(uint2*)(P2 + off) = *(uint2*)d2;
}

// ---------------------------------------------------------------------------
// V transpose + int8 quantize into packed vT tiles (rows = bz*EDIM+e, K=SEQ).
// ---------------------------------------------------------------------------
__global__ void __launch_bounds__(256)
transpose_v(const float* __restrict__ Qf,
            signed char* __restrict__ T1, signed char* __restrict__ T2)
{
    __shared__ signed char t1[32][33];
    __shared__ signed char t2[32][33];
    const int b  = blockIdx.z;
    const int t0 = blockIdx.x * 32;
    const int e0 = blockIdx.y * 32;
    const int tx = threadIdx.x;
    const int ty = threadIdx.y;
    const float inv = 127.0f / fmaxf(__uint_as_float(g_amax[0]), 1e-20f);
#pragma unroll
    for (int rr = 0; rr < 32; rr += 8) {
        const int row = ty + rr;
        const long long src = (long long)(b * SEQ + t0 + row) * F3E + 2 * EDIM + e0 + tx;
        signed char d1, d2;
        quant2(Qf[src], inv, d1, d2);
        t1[row][tx] = d1;
        t2[row][tx] = d2;
    }
    __syncthreads();
#pragma unroll
    for (int rr = 0; rr < 32; rr += 8) {
        const int row = ty + rr;
        const int fr = b * EDIM + e0 + row;       // global feature row
        const long long off = pkidx(fr, t0 + tx, SEQ / 64);
        T1[off] = t1[tx][row];
        T2[off] = t2[tx][row];
    }
}

// ---------------------------------------------------------------------------
// Launch
// ---------------------------------------------------------------------------
extern "C" void kernel_launch(void* const* d_in, const int* in_sizes, int n_in,
                              void* d_out, int out_size)
{
    const float* x = (const float*)d_in[0];   // [4, 2048, 1024]
    const float* W = (const float*)d_in[1];   // [3072, 1024]
    float* out = (float*)d_out;               // [4, 2048, 1024]

    signed char *x1, *x2, *w1, *w2, *q1, *q2, *k1, *k2, *p1, *p2, *vt1, *vt2;
    float *qkvf, *sc, *pscale, *sx, *sw, *sq, *sk;
    cudaGetSymbolAddress((void**)&x1, g_x1);
    cudaGetSymbolAddress((void**)&x2, g_x2);
    cudaGetSymbolAddress((void**)&w1, g_w1);
    cudaGetSymbolAddress((void**)&w2, g_w2);
    cudaGetSymbolAddress((void**)&qkvf, g_qkvf);
    cudaGetSymbolAddress((void**)&q1, g_q1);
    cudaGetSymbolAddress((void**)&q2, g_q2);
    cudaGetSymbolAddress((void**)&k1, g_k1);
    cudaGetSymbolAddress((void**)&k2, g_k2);
    cudaGetSymbolAddress((void**)&sc, g_s);
    cudaGetSymbolAddress((void**)&p1, g_p1);
    cudaGetSymbolAddress((void**)&p2, g_p2);
    cudaGetSymbolAddress((void**)&pscale, g_pscale);
    cudaGetSymbolAddress((void**)&vt1, g_vt1);
    cudaGetSymbolAddress((void**)&vt2, g_vt2);
    cudaGetSymbolAddress((void**)&sx, g_sx);
    cudaGetSymbolAddress((void**)&sw, g_sw);
    cudaGetSymbolAddress((void**)&sq, g_sq);
    cudaGetSymbolAddress((void**)&sk, g_sk);

    cudaFuncSetAttribute(gemm_i8<1,1>, cudaFuncAttributeMaxDynamicSharedMemorySize, SMEM_I8);
    cudaFuncSetAttribute(gemm_i8<0,1>, cudaFuncAttributeMaxDynamicSharedMemorySize, SMEM_I8);
    cudaFuncSetAttribute(gemm_i8<0,0>, cudaFuncAttributeMaxDynamicSharedMemorySize, SMEM_I8);

    // 1) init v amax; per-row quantize x and W into packed tiles
    amax_init<<<1, 32>>>();
    quant_row<<<MROWS, 256>>>(x, EDIM, x1, x2, sx, 1.0f, EDIM / 64);
    quant_row<<<F3E,   256>>>(W, EDIM, w1, w2, sw, 1.0f, EDIM / 64);

    // 2) qkv = x @ W^T  (fp32 out; scale sx[row]*sw[col]; track v amax)
    gemm_i8<1,1><<<dim3(F3E / BNI, MROWS / BMI, 1), 256, SMEM_I8>>>(
        x1, x2, w1, w2, qkvf,
        0, 0, F3E, EDIM, 0,
        sx, 0, sw, 0, 1.0f);

    // 3) per-row quantize q (fold 1/32) and k; transpose+quantize v
    quant_row<<<MROWS, 256>>>(qkvf,        F3E, q1, q2, sq, 1.0f / 32.0f, EDIM / 64);
    quant_row<<<MROWS, 256>>>(qkvf + EDIM, F3E, k1, k2, sk, 1.0f, EDIM / 64);
    transpose_v<<<dim3(SEQ / 32, EDIM / 32, BATCH), dim3(32, 8)>>>(qkvf, vt1, vt2);

    // 4) scores[b] = (Q @ K^T)/32   (scale sq[row]*sk[col], 1/32 in sq)
    gemm_i8<0,1><<<dim3(SEQ / BNI, SEQ / BMI, BATCH), 256, SMEM_I8>>>(
        q1, q2, k1, k2, sc,
        SEQ, SEQ, SEQ, EDIM, (long long)SEQ * SEQ,
        sq, SEQ, sk, SEQ, 1.0f);

    // 5) softmax -> packed int8 P digits + per-row scale
    softmax_q<<<BATCH * SEQ, 256>>>(sc, p1, p2, pscale);

    // 6) out[b] = P @ V  (scale pscale[row] * vAmax/127)
    gemm_i8<0,0><<<dim3(EDIM / BNI, SEQ / BMI, BATCH), 256, SMEM_I8>>>(
        p1, p2, vt1, vt2, out,
        SEQ, EDIM, EDIM, SEQ, (long long)SEQ * EDIM,
        pscale, SEQ, (const float*)nullptr, 0, 1.0f);
}

// round 17
// speedup vs baseline: 1.0280x; 1.0280x over previous
#include <cuda_runtime.h>
#include <cuda_bf16.h>
#include <math.h>
#include <stdint.h>

// ---------------------------------------------------------------------------
// Single-head self-attention, B=4, N=2048, E=1024, fp32.
// ALL GEMMs: int8 IMMA, two-digit fixed point (3 mmas / k32, 2 accumulators).
// R17 (= R15 revert + merged q/k quant): operands as pre-swizzled 128x128B
// tiles; GEMM loads chunks via cp.async.bulk (4 instrs/chunk) + mbarrier,
// BK=128, 2-stage, 2 CTAs/SM.
// ---------------------------------------------------------------------------

#define BATCH 4
#define SEQ   2048
#define EDIM  1024
#define MROWS (BATCH * SEQ)      // 8192
#define F3E   (3 * EDIM)         // 3072

// ---- device scratch (alloc-free rule) ----
// packed int8 digit arrays (tile layout: [row>>7][k>>7] 16KB tiles, SW128)
__device__ signed char  g_x1[MROWS * EDIM];
__device__ signed char  g_x2[MROWS * EDIM];
__device__ signed char  g_w1[F3E * EDIM];
__device__ signed char  g_w2[F3E * EDIM];
__device__ float        g_qkvf[(long long)MROWS * F3E];       // fp32 qkv
__device__ signed char  g_q1[MROWS * EDIM];
__device__ signed char  g_q2[MROWS * EDIM];
__device__ signed char  g_k1[MROWS * EDIM];
__device__ signed char  g_k2[MROWS * EDIM];
__device__ float        g_s[(long long)BATCH * SEQ * SEQ];    // scores fp32
__device__ signed char  g_p1[(long long)BATCH * SEQ * SEQ];   // P digit 1
__device__ signed char  g_p2[(long long)BATCH * SEQ * SEQ];   // P digit 2
__device__ float        g_pscale[MROWS];                      // per-row P scale
__device__ signed char  g_vt1[BATCH * EDIM * SEQ];            // V^T digit 1
__device__ signed char  g_vt2[BATCH * EDIM * SEQ];            // V^T digit 2
__device__ float        g_sx[MROWS];    // per-row x scale   (amax/127)
__device__ float        g_sw[F3E];      // per-row W scale
__device__ float        g_sq[MROWS];    // per-row q scale (x 1/32 folded)
__device__ float        g_sk[MROWS];    // per-row k scale
__device__ unsigned int g_amax[1];      // v global amax (fp32 bits)

// ---------------------------------------------------------------------------
// PTX helpers
// ---------------------------------------------------------------------------
__device__ __forceinline__ uint32_t s2u(const void* p) {
    uint32_t a;
    asm("{ .reg .u64 t; cvta.to.shared.u64 t, %1; cvt.u32.u64 %0, t; }"
        : "=r"(a) : "l"(p));
    return a;
}
__device__ __forceinline__ void ldsm4(uint32_t* r, uint32_t addr) {
    asm volatile("ldmatrix.sync.aligned.m8n8.x4.shared.b16 {%0,%1,%2,%3}, [%4];"
                 : "=r"(r[0]), "=r"(r[1]), "=r"(r[2]), "=r"(r[3]) : "r"(addr));
}
__device__ __forceinline__ void mma_s8(int* c, const uint32_t* a,
                                       uint32_t b0, uint32_t b1) {
    asm volatile("mma.sync.aligned.m16n8k32.row.col.s32.s8.s8.s32 "
                 "{%0,%1,%2,%3}, {%4,%5,%6,%7}, {%8,%9}, {%0,%1,%2,%3};"
                 : "+r"(c[0]), "+r"(c[1]), "+r"(c[2]), "+r"(c[3])
                 : "r"(a[0]), "r"(a[1]), "r"(a[2]), "r"(a[3]),
                   "r"(b0), "r"(b1));
}
// SW128 swizzle within a 128x128B tile
__device__ __forceinline__ uint32_t swz128(uint32_t r, uint32_t s) {
    return r * 128u + ((s ^ (r & 7u)) << 4);
}
// packed tile index: byte offset of (row, k) in a [rows x K] int8 array stored
// as row-tile-major 16KB SW128 tiles. kt = K/128.
__device__ __forceinline__ long long pkidx(int row, int k, int kt) {
    long long tile = (long long)(row >> 7) * kt + (k >> 7);
    uint32_t within = swz128((uint32_t)(row & 127), (uint32_t)((k >> 4) & 7))
                    + (uint32_t)(k & 15);
    return tile * 16384 + (long long)within;
}
// two-digit int8 quantization:  a ~= scale*(d1 + d2/254),  scale = amax/127
__device__ __forceinline__ void quant2(float a, float inv,
                                       signed char& d1, signed char& d2) {
    float t  = a * inv;
    float r1 = rintf(t);
    r1 = fminf(fmaxf(r1, -127.0f), 127.0f);
    float r2 = rintf((t - r1) * 254.0f);
    r2 = fminf(fmaxf(r2, -127.0f), 127.0f);
    d1 = (signed char)(int)r1;
    d2 = (signed char)(int)r2;
}

#define MBAR_INIT(mb, c) asm volatile("mbarrier.init.shared.b64 [%0], %1;" :: "r"(mb), "r"(c) : "memory")
#define MBAR_EXPECT(mb, bytes) asm volatile("mbarrier.arrive.expect_tx.shared.b64 _, [%0], %1;" :: "r"(mb), "r"(bytes) : "memory")
#define MBAR_WAIT(mb, ph) do {                                                   \
    asm volatile("{\n\t.reg .pred P;\n\t"                                        \
        "WL_%=:\n\t"                                                             \
        "mbarrier.try_wait.parity.shared.b64 P, [%0], %1;\n\t"                   \
        "@P bra.uni WD_%=;\n\t"                                                  \
        "bra.uni WL_%=;\n\t"                                                     \
        "WD_%=:\n\t}" :: "r"((uint32_t)(mb)), "r"((uint32_t)(ph)) : "memory");   \
} while (0)

__device__ __forceinline__ void bulk_ld(uint32_t dst, const void* src,
                                        uint32_t bytes, uint32_t mbar) {
    asm volatile("cp.async.bulk.shared::cluster.global.mbarrier::complete_tx::bytes "
                 "[%0], [%1], %2, [%3];"
                 :: "r"(dst), "l"(src), "r"(bytes), "r"(mbar) : "memory");
}

// ---------------------------------------------------------------------------
// init (v amax only)
// ---------------------------------------------------------------------------
__global__ void amax_init() {
    if (threadIdx.x == 0) g_amax[0] = 0u;
}

// ---------------------------------------------------------------------------
// Per-row quantize into PACKED tile layout. One block per 1024-elem row.
// ---------------------------------------------------------------------------
__global__ void __launch_bounds__(256)
quant_row(const float* __restrict__ in, long long inStride,
          signed char* __restrict__ d1, signed char* __restrict__ d2,
          float* __restrict__ scale, float preScale, int kt)
{
    const int row = blockIdx.x;
    const int t   = threadIdx.x;
    __shared__ float red[8];

    const float4 v = *(const float4*)(in + (long long)row * inStride + t * 4);
    float m = fmaxf(fmaxf(fabsf(v.x), fabsf(v.y)),
                    fmaxf(fabsf(v.z), fabsf(v.w)));
#pragma unroll
    for (int o = 16; o > 0; o >>= 1)
        m = fmaxf(m, __shfl_xor_sync(0xffffffffu, m, o));
    if ((t & 31) == 0) red[t >> 5] = m;
    __syncthreads();
    float amax = red[0];
#pragma unroll
    for (int i = 1; i < 8; i++) amax = fmaxf(amax, red[i]);
    amax = fmaxf(amax, 1e-20f);

    if (t == 0) scale[row] = (amax / 127.0f) * preScale;

    const float inv = 127.0f / amax;
    signed char a1, a2, b1, b2, c1, c2, e1, e2;
    quant2(v.x, inv, a1, a2);
    quant2(v.y, inv, b1, b2);
    quant2(v.z, inv, c1, c2);
    quant2(v.w, inv, e1, e2);
    const long long off = pkidx(row, t * 4, kt);
    *(char4*)(d1 + off) = make_char4(a1, b1, c1, e1);
    *(char4*)(d2 + off) = make_char4(a2, b2, c2, e2);
}

// ---------------------------------------------------------------------------
// Merged q+k quantize from qkvf: blocks 0..MROWS-1 -> q, MROWS.. -> k.
// ---------------------------------------------------------------------------
__global__ void __launch_bounds__(256)
quant_qk2(const float* __restrict__ qkvf,
          signed char* __restrict__ q1, signed char* __restrict__ q2,
          signed char* __restrict__ k1, signed char* __restrict__ k2,
          float* __restrict__ sq, float* __restrict__ sk)
{
    const int isK  = (blockIdx.x >= MROWS);
    const int row  = isK ? blockIdx.x - MROWS : blockIdx.x;
    const int t    = threadIdx.x;
    __shared__ float red[8];

    const float* in = qkvf + (long long)row * F3E + (isK ? EDIM : 0);
    const float4 v = *(const float4*)(in + t * 4);
    float m = fmaxf(fmaxf(fabsf(v.x), fabsf(v.y)),
                    fmaxf(fabsf(v.z), fabsf(v.w)));
#pragma unroll
    for (int o = 16; o > 0; o >>= 1)
        m = fmaxf(m, __shfl_xor_sync(0xffffffffu, m, o));
    if ((t & 31) == 0) red[t >> 5] = m;
    __syncthreads();
    float amax = red[0];
#pragma unroll
    for (int i = 1; i < 8; i++) amax = fmaxf(amax, red[i]);
    amax = fmaxf(amax, 1e-20f);

    if (t == 0) {
        if (isK) sk[row] = amax / 127.0f;
        else     sq[row] = (amax / 127.0f) * (1.0f / 32.0f);
    }

    const float inv = 127.0f / amax;
    signed char a1, a2, b1, b2, c1, c2, e1, e2;
    quant2(v.x, inv, a1, a2);
    quant2(v.y, inv, b1, b2);
    quant2(v.z, inv, c1, c2);
    quant2(v.w, inv, e1, e2);
    const long long off = pkidx(row, t * 4, EDIM / 128);
    signed char* d1 = isK ? k1 : q1;
    signed char* d2 = isK ? k2 : q2;
    *(char4*)(d1 + off) = make_char4(a1, b1, c1, e1);
    *(char4*)(d2 + off) = make_char4(a2, b2, c2, e2);
}

// ---------------------------------------------------------------------------
// int8 two-digit NT GEMM, bulk-copy pipeline (R15 config).
//   C[m,n] = rowScaleA[m] * colScale(n) * alpha * (acc1 + acc2/254)
// Block 128(M)x64(N), BK=128, 256 threads, 8 warps 4(M)x2(N), warp 32x32,
// 2-stage cp.async.bulk + mbarrier, 2 CTAs/SM.
// AMAXV=1: atomicMax |C| into g_amax[0] for cols >= 2048 (v region of qkv).
// ---------------------------------------------------------------------------
#define BMI 128
#define BNI 64
#define TILE_A 16384
#define TILE_B 8192
#define STAGE (2 * TILE_A + 2 * TILE_B)    // 49152
#define OFF_A1 0
#define OFF_A2 TILE_A
#define OFF_B1 (2 * TILE_A)
#define OFF_B2 (2 * TILE_A + TILE_B)
#define SMEM_I8 (2048 + 2 * STAGE)

template <int AMAXV, int COLB>
__global__ void __launch_bounds__(256, 2)
gemm_i8(const signed char* __restrict__ A1, const signed char* __restrict__ A2,
        const signed char* __restrict__ B1, const signed char* __restrict__ B2,
        float* __restrict__ C,
        int aRows, int bRows, int ldc, int K,
        long long sC,
        const float* __restrict__ rowScaleA, int rsStride,
        const float* __restrict__ colScaleB, int csStride,
        float alpha)
{
    extern __shared__ char dsm[];
    const uint32_t raw   = s2u(dsm);
    const uint32_t base  = (raw + 1023u) & ~1023u;
    const uint32_t mbar0 = base;                 // two mbars at +0, +8
    const uint32_t tile0 = base + 1024;

    const int tid  = threadIdx.x;
    const int wid  = tid >> 5;
    const int lane = tid & 31;
    const int wm   = wid & 3;       // 0..3 -> M (32 rows each)
    const int wn   = wid >> 2;      // 0..1 -> N (32 cols each)
    const int bz   = blockIdx.z;
    const int row0 = blockIdx.y * BMI;
    const int col0 = blockIdx.x * BNI;
    const int ktN  = K >> 7;
    const int aRow0 = bz * aRows + row0;          // multiple of 128
    const int bRow0 = bz * bRows + col0;          // multiple of 64
    const long long aTileRow = (long long)(aRow0 >> 7) * ktN;
    const long long bTileRow = (long long)(bRow0 >> 7) * ktN;
    const long long bSub = (bRow0 & 64) ? TILE_B : 0;

    if (tid == 0) {
        MBAR_INIT(mbar0, 1);
        MBAR_INIT(mbar0 + 8, 1);
    }
    __syncthreads();

    auto issue = [&](int i) {
        const uint32_t sb = tile0 + (uint32_t)(i & 1) * STAGE;
        const uint32_t mb = mbar0 + (uint32_t)(i & 1) * 8;
        MBAR_EXPECT(mb, (uint32_t)STAGE);
        const long long tA = (aTileRow + i) * 16384;
        const long long tB = (bTileRow + i) * 16384 + bSub;
        bulk_ld(sb + OFF_A1, A1 + tA, TILE_A, mb);
        bulk_ld(sb + OFF_A2, A2 + tA, TILE_A, mb);
        bulk_ld(sb + OFF_B1, B1 + tB, TILE_B, mb);
        bulk_ld(sb + OFF_B2, B2 + tB, TILE_B, mb);
    };

    const int nch = K >> 7;   // BK=128
    if (tid == 0) {
        issue(0);
        issue(1);
    }

    int acc1[2][4][4], acc2[2][4][4];
#pragma unroll
    for (int t = 0; t < 2; t++)
#pragma unroll
        for (int u = 0; u < 4; u++)
#pragma unroll
            for (int j = 0; j < 4; j++) { acc1[t][u][j] = 0; acc2[t][u][j] = 0; }

    const uint32_t lrow  = (uint32_t)(lane & 15);
    const uint32_t lhalf = (uint32_t)(lane >> 4);

    for (int i = 0; i < nch; i++) {
        MBAR_WAIT(mbar0 + (uint32_t)(i & 1) * 8, (i >> 1) & 1);

        const uint32_t sb = tile0 + (uint32_t)(i & 1) * STAGE;
        const uint32_t a1s = sb + OFF_A1;
        const uint32_t a2s = sb + OFF_A2;
        const uint32_t b1s = sb + OFF_B1;
        const uint32_t b2s = sb + OFF_B2;

#pragma unroll
        for (int ks = 0; ks < 4; ks++) {
            const uint32_t slot = (uint32_t)(ks * 2) + lhalf;
            uint32_t b1f[2][4], b2f[2][4];
#pragma unroll
            for (int g = 0; g < 2; g++) {
                const uint32_t r = (uint32_t)(wn * 32 + g * 16) + lrow;
                const uint32_t ro = swz128(r, slot);
                ldsm4(b1f[g], b1s + ro);
                ldsm4(b2f[g], b2s + ro);
            }
            uint32_t a1f[2][4], a2f[2][4];
#pragma unroll
            for (int t = 0; t < 2; t++) {
                const uint32_t r = (uint32_t)(wm * 32 + t * 16) + lrow;
                const uint32_t ro = swz128(r, slot);
                ldsm4(a1f[t], a1s + ro);
                ldsm4(a2f[t], a2s + ro);
            }
#pragma unroll
            for (int t = 0; t < 2; t++)
#pragma unroll
                for (int u = 0; u < 4; u++)
                    mma_s8(acc1[t][u], a1f[t], b1f[u >> 1][u & 1], b1f[u >> 1][(u & 1) + 2]);
#pragma unroll
            for (int t = 0; t < 2; t++)
#pragma unroll
                for (int u = 0; u < 4; u++)
                    mma_s8(acc2[t][u], a1f[t], b2f[u >> 1][u & 1], b2f[u >> 1][(u & 1) + 2]);
#pragma unroll
            for (int t = 0; t < 2; t++)
#pragma unroll
                for (int u = 0; u < 4; u++)
                    mma_s8(acc2[t][u], a2f[t], b1f[u >> 1][u & 1], b1f[u >> 1][(u & 1) + 2]);
        }

        __syncthreads();   // all warps done reading stage i&1
        if (tid == 0 && i + 2 < nch) issue(i + 2);
    }

    // ---- epilogue
    float sBglob = alpha;
    if (!COLB)
        sBglob *= fmaxf(__uint_as_float(g_amax[0]), 1e-20f) / 127.0f;
    const int er = lane >> 2;
    const int ec = 2 * (lane & 3);
    float lmax = 0.0f;
#pragma unroll
    for (int t = 0; t < 2; t++) {
        const int rloc = wm * 32 + t * 16 + er;
        const float s0 = rowScaleA[bz * rsStride + row0 + rloc] * sBglob;
        const float s1 = rowScaleA[bz * rsStride + row0 + rloc + 8] * sBglob;
        const long long r0r = row0 + rloc;
#pragma unroll
        for (int u = 0; u < 4; u++) {
            const int cc = col0 + wn * 32 + u * 8 + ec;
            float cs0 = 1.0f, cs1 = 1.0f;
            if (COLB) {
                cs0 = colScaleB[bz * csStride + cc];
                cs1 = colScaleB[bz * csStride + cc + 1];
            }
            float v[4];
            v[0] = s0 * cs0 * ((float)acc1[t][u][0] + (float)acc2[t][u][0] * (1.0f / 254.0f));
            v[1] = s0 * cs1 * ((float)acc1[t][u][1] + (float)acc2[t][u][1] * (1.0f / 254.0f));
            v[2] = s1 * cs0 * ((float)acc1[t][u][2] + (float)acc2[t][u][2] * (1.0f / 254.0f));
            v[3] = s1 * cs1 * ((float)acc1[t][u][3] + (float)acc2[t][u][3] * (1.0f / 254.0f));
            if (AMAXV && col0 >= 2048)
                lmax = fmaxf(fmaxf(fmaxf(fabsf(v[0]), fabsf(v[1])),
                                   fmaxf(fabsf(v[2]), fabsf(v[3]))), lmax);
            *(float2*)(C + (long long)bz * sC + r0r * ldc + cc)       = make_float2(v[0], v[1]);
            *(float2*)(C + (long long)bz * sC + (r0r + 8) * ldc + cc) = make_float2(v[2], v[3]);
        }
    }
    if (AMAXV && col0 >= 2048) {
#pragma unroll
        for (int o = 16; o > 0; o >>= 1)
            lmax = fmaxf(lmax, __shfl_xor_sync(0xffffffffu, lmax, o));
        if (lane == 0)
            atomicMax(&g_amax[0], __float_as_uint(lmax));
    }
}

// ---------------------------------------------------------------------------
// Row softmax (2048 cols) fp32 -> two-digit int8 P (packed, kt=16) + scale.
// ---------------------------------------------------------------------------
__global__ void __launch_bounds__(256)
softmax_q(const float* __restrict__ S, signed char* __restrict__ P1,
          signed char* __restrict__ P2, float* __restrict__ pscale)
{
    const int rowg = blockIdx.x;                    // global row 0..8191
    const long long roff = (long long)rowg * SEQ;
    const float* row = S + roff;
    const int t = threadIdx.x;
    __shared__ float red[8];

    float v[8];
    float4 a = *(const float4*)(row + t * 8);
    float4 b = *(const float4*)(row + t * 8 + 4);
    v[0] = a.x; v[1] = a.y; v[2] = a.z; v[3] = a.w;
    v[4] = b.x; v[5] = b.y; v[6] = b.z; v[7] = b.w;

    float m = -INFINITY;
#pragma unroll
    for (int i = 0; i < 8; i++) m = fmaxf(m, v[i]);
#pragma unroll
    for (int o = 16; o > 0; o >>= 1)
        m = fmaxf(m, __shfl_xor_sync(0xffffffffu, m, o));
    if ((t & 31) == 0) red[t >> 5] = m;
    __syncthreads();
    float rmax = red[0];
#pragma unroll
    for (int i = 1; i < 8; i++) rmax = fmaxf(rmax, red[i]);
    __syncthreads();

    float s = 0.0f;
#pragma unroll
    for (int i = 0; i < 8; i++) {
        v[i] = expf(v[i] - rmax);
        s += v[i];
    }
#pragma unroll
    for (int o = 16; o > 0; o >>= 1)
        s += __shfl_xor_sync(0xffffffffu, s, o);
    if ((t & 31) == 0) red[t >> 5] = s;
    __syncthreads();
    float rsum = 0.0f;
#pragma unroll
    for (int i = 0; i < 8; i++) rsum += red[i];

    if (t == 0) pscale[rowg] = (1.0f / rsum) / 127.0f;

    signed char d1[8], d2[8];
#pragma unroll
    for (int i = 0; i < 8; i++)
        quant2(v[i], 127.0f, d1[i], d2[i]);
    const long long off = pkidx(rowg, t * 8, SEQ / 128);
    *(uint2*)(P1 + off) = *(uint2*)d1;
    *(uint2*)(P2 + off) = *(uint2*)d2;
}

// ---------------------------------------------------------------------------
// V transpose + int8 quantize into packed vT tiles (rows = bz*EDIM+e, K=SEQ).
// ---------------------------------------------------------------------------
__global__ void __launch_bounds__(256)
transpose_v(const float* __restrict__ Qf,
            signed char* __restrict__ T1, signed char* __restrict__ T2)
{
    __shared__ signed char t1[32][33];
    __shared__ signed char t2[32][33];
    const int b  = blockIdx.z;
    const int t0 = blockIdx.x * 32;
    const int e0 = blockIdx.y * 32;
    const int tx = threadIdx.x;
    const int ty = threadIdx.y;
    const float inv = 127.0f / fmaxf(__uint_as_float(g_amax[0]), 1e-20f);
#pragma unroll
    for (int rr = 0; rr < 32; rr += 8) {
        const int row = ty + rr;
        const long long src = (long long)(b * SEQ + t0 + row) * F3E + 2 * EDIM + e0 + tx;
        signed char d1, d2;
        quant2(Qf[src], inv, d1, d2);
        t1[row][tx] = d1;
        t2[row][tx] = d2;
    }
    __syncthreads();
#pragma unroll
    for (int rr = 0; rr < 32; rr += 8) {
        const int row = ty + rr;
        const int fr = b * EDIM + e0 + row;       // global feature row
        const long long off = pkidx(fr, t0 + tx, SEQ / 128);
        T1[off] = t1[tx][row];
        T2[off] = t2[tx][row];
    }
}

// ---------------------------------------------------------------------------
// Launch
// ---------------------------------------------------------------------------
extern "C" void kernel_launch(void* const* d_in, const int* in_sizes, int n_in,
                              void* d_out, int out_size)
{
    const float* x = (const float*)d_in[0];   // [4, 2048, 1024]
    const float* W = (const float*)d_in[1];   // [3072, 1024]
    float* out = (float*)d_out;               // [4, 2048, 1024]

    signed char *x1, *x2, *w1, *w2, *q1, *q2, *k1, *k2, *p1, *p2, *vt1, *vt2;
    float *qkvf, *sc, *pscale, *sx, *sw, *sq, *sk;
    cudaGetSymbolAddress((void**)&x1, g_x1);
    cudaGetSymbolAddress((void**)&x2, g_x2);
    cudaGetSymbolAddress((void**)&w1, g_w1);
    cudaGetSymbolAddress((void**)&w2, g_w2);
    cudaGetSymbolAddress((void**)&qkvf, g_qkvf);
    cudaGetSymbolAddress((void**)&q1, g_q1);
    cudaGetSymbolAddress((void**)&q2, g_q2);
    cudaGetSymbolAddress((void**)&k1, g_k1);
    cudaGetSymbolAddress((void**)&k2, g_k2);
    cudaGetSymbolAddress((void**)&sc, g_s);
    cudaGetSymbolAddress((void**)&p1, g_p1);
    cudaGetSymbolAddress((void**)&p2, g_p2);
    cudaGetSymbolAddress((void**)&pscale, g_pscale);
    cudaGetSymbolAddress((void**)&vt1, g_vt1);
    cudaGetSymbolAddress((void**)&vt2, g_vt2);
    cudaGetSymbolAddress((void**)&sx, g_sx);
    cudaGetSymbolAddress((void**)&sw, g_sw);
    cudaGetSymbolAddress((void**)&sq, g_sq);
    cudaGetSymbolAddress((void**)&sk, g_sk);

    cudaFuncSetAttribute(gemm_i8<1,1>, cudaFuncAttributeMaxDynamicSharedMemorySize, SMEM_I8);
    cudaFuncSetAttribute(gemm_i8<0,1>, cudaFuncAttributeMaxDynamicSharedMemorySize, SMEM_I8);
    cudaFuncSetAttribute(gemm_i8<0,0>, cudaFuncAttributeMaxDynamicSharedMemorySize, SMEM_I8);

    // 1) init v amax; per-row quantize x and W into packed tiles
    amax_init<<<1, 32>>>();
    quant_row<<<MROWS, 256>>>(x, EDIM, x1, x2, sx, 1.0f, EDIM / 128);
    quant_row<<<F3E,   256>>>(W, EDIM, w1, w2, sw, 1.0f, EDIM / 128);

    // 2) qkv = x @ W^T  (fp32 out; scale sx[row]*sw[col]; track v amax)
    gemm_i8<1,1><<<dim3(F3E / BNI, MROWS / BMI, 1), 256, SMEM_I8>>>(
        x1, x2, w1, w2, qkvf,
        0, 0, F3E, EDIM, 0,
        sx, 0, sw, 0, 1.0f);

    // 3) merged per-row quantize of q (1/32 folded) and k; transpose+quant v
    quant_qk2<<<2 * MROWS, 256>>>(qkvf, q1, q2, k1, k2, sq, sk);
    transpose_v<<<dim3(SEQ / 32, EDIM / 32, BATCH), dim3(32, 8)>>>(qkvf, vt1, vt2);

    // 4) scores[b] = (Q @ K^T)/32   (scale sq[row]*sk[col], 1/32 in sq)
    gemm_i8<0,1><<<dim3(SEQ / BNI, SEQ / BMI, BATCH), 256, SMEM_I8>>>(
        q1, q2, k1, k2, sc,
        SEQ, SEQ, SEQ, EDIM, (long long)SEQ * SEQ,
        sq, SEQ, sk, SEQ, 1.0f);

    // 5) softmax -> packed int8 P digits + per-row scale
    softmax_q<<<BATCH * SEQ, 256>>>(sc, p1, p2, pscale);

    // 6) out[b] = P @ V  (scale pscale[row] * vAmax/127)
    gemm_i8<0,0><<<dim3(EDIM / BNI, SEQ / BMI, BATCH), 256, SMEM_I8>>>(
        p1, p2, vt1, vt2, out,
        SEQ, EDIM, EDIM, SEQ, (long long)SEQ * EDIM,
        pscale, SEQ, (const float*)nullptr, 0, 1.0f);
}